// round 2
// baseline (speedup 1.0000x reference)
#include <cuda_runtime.h>
#include <cuda_bf16.h>

// support: (2,5,1024,128) -> d_in[0]
// query:   (2,4,1024,128) -> d_in[1]
// out:     (2,4,5,1024,1024) fp32
// sim[b,i,j,m,n] = dot(q[b,i,m,:], s[b,j,n,:]) * rq[b,i,m] * rs[b,j,n]

#define NQ_ROWS (2*4*1024)   // 8192
#define NS_ROWS (2*5*1024)   // 10240
#define KDIM 128

__device__ float g_rq[NQ_ROWS];
__device__ float g_rs[NS_ROWS];

// ---------------------------------------------------------------------------
// Kernel 1: per-row inverse L2 norm. One warp per row, one float4 per lane.
// ---------------------------------------------------------------------------
__global__ void row_rnorm_kernel(const float* __restrict__ s,
                                 const float* __restrict__ q) {
    int warp_id = (blockIdx.x * blockDim.x + threadIdx.x) >> 5;
    int lane    = threadIdx.x & 31;
    if (warp_id >= NQ_ROWS + NS_ROWS) return;

    const float* base;
    float* outp;
    if (warp_id < NQ_ROWS) {
        base = q + (size_t)warp_id * KDIM;
        outp = &g_rq[warp_id];
    } else {
        int r = warp_id - NQ_ROWS;
        base = s + (size_t)r * KDIM;
        outp = &g_rs[r];
    }

    float4 v = *reinterpret_cast<const float4*>(base + lane * 4);
    float ss = v.x * v.x + v.y * v.y + v.z * v.z + v.w * v.w;
    #pragma unroll
    for (int off = 16; off > 0; off >>= 1)
        ss += __shfl_xor_sync(0xffffffffu, ss, off);
    if (lane == 0)
        *outp = 1.0f / fmaxf(sqrtf(ss), 1e-12f);
}

// ---------------------------------------------------------------------------
// Kernel 2: batched NT GEMM with cosine epilogue.
// BM=BN=128, BK=32, 256 threads, 8x8 per-thread tile in split-fragment
// layout (rows tr*4+r and 64+tr*4+r; cols tc*4+c and 64+tc*4+c) so all
// LDS.128 fragment loads are conflict-free.
// ---------------------------------------------------------------------------
#define BM 128
#define BN 128
#define BK 32
#define LDS_STRIDE (BM + 4)   // 132 floats; 132*4=528 bytes, 16B-aligned rows

__global__ __launch_bounds__(256)
void cosine_gemm_kernel(const float* __restrict__ s,
                        const float* __restrict__ q,
                        float* __restrict__ out) {
    __shared__ float As[BK][LDS_STRIDE];  // As[k][m]
    __shared__ float Bs[BK][LDS_STRIDE];  // Bs[k][n]

    int p  = blockIdx.z;          // (b*4+i)*5 + j
    int b  = p / 20;
    int ij = p % 20;
    int i  = ij / 5;
    int j  = ij % 5;

    const float* qbase = q + (size_t)((b * 4 + i) * 1024) * KDIM;
    const float* sbase = s + (size_t)((b * 5 + j) * 1024) * KDIM;

    int m0 = blockIdx.y * BM;
    int n0 = blockIdx.x * BN;

    int tid = threadIdx.x;
    int tr  = tid >> 4;   // 0..15
    int tc  = tid & 15;   // 0..15

    float acc[8][8];
    #pragma unroll
    for (int r = 0; r < 8; r++)
        #pragma unroll
        for (int c = 0; c < 8; c++)
            acc[r][c] = 0.0f;

    for (int kc = 0; kc < KDIM; kc += BK) {
        // Stage: 128 rows x 32 k per tile = 1024 float4; 4 per thread.
        #pragma unroll
        for (int it = 0; it < 4; it++) {
            int lin = tid + it * 256;       // 0..1023
            int row = lin >> 3;             // 0..127
            int kk  = (lin & 7) * 4;        // 0..28
            float4 va = *reinterpret_cast<const float4*>(
                qbase + (size_t)(m0 + row) * KDIM + kc + kk);
            As[kk + 0][row] = va.x;
            As[kk + 1][row] = va.y;
            As[kk + 2][row] = va.z;
            As[kk + 3][row] = va.w;
            float4 vb = *reinterpret_cast<const float4*>(
                sbase + (size_t)(n0 + row) * KDIM + kc + kk);
            Bs[kk + 0][row] = vb.x;
            Bs[kk + 1][row] = vb.y;
            Bs[kk + 2][row] = vb.z;
            Bs[kk + 3][row] = vb.w;
        }
        __syncthreads();

        #pragma unroll
        for (int k = 0; k < BK; k++) {
            float4 a0 = *reinterpret_cast<const float4*>(&As[k][tr * 4]);
            float4 a1 = *reinterpret_cast<const float4*>(&As[k][64 + tr * 4]);
            float4 b0 = *reinterpret_cast<const float4*>(&Bs[k][tc * 4]);
            float4 b1 = *reinterpret_cast<const float4*>(&Bs[k][64 + tc * 4]);
            float a[8] = {a0.x, a0.y, a0.z, a0.w, a1.x, a1.y, a1.z, a1.w};
            float bb[8] = {b0.x, b0.y, b0.z, b0.w, b1.x, b1.y, b1.z, b1.w};
            #pragma unroll
            for (int r = 0; r < 8; r++)
                #pragma unroll
                for (int c = 0; c < 8; c++)
                    acc[r][c] = fmaf(a[r], bb[c], acc[r][c]);
        }
        __syncthreads();
    }

    // Epilogue: scale by inverse norms, store two float4 per row-slice.
    int qrow = (b * 4 + i) * 1024 + m0;
    int srow = (b * 5 + j) * 1024 + n0;

    float rsv[8];
    #pragma unroll
    for (int c = 0; c < 4; c++) {
        rsv[c]     = g_rs[srow + tc * 4 + c];
        rsv[c + 4] = g_rs[srow + 64 + tc * 4 + c];
    }

    size_t obase = (size_t)p << 20;  // p * 1024 * 1024
    #pragma unroll
    for (int r = 0; r < 8; r++) {
        int ml = (r < 4) ? (tr * 4 + r) : (64 + tr * 4 + r - 4);
        int m  = m0 + ml;
        float rmv = g_rq[qrow + ml];
        float* orow = out + obase + (size_t)m * 1024 + n0;
        float4 o0, o1;
        o0.x = acc[r][0] * rmv * rsv[0];
        o0.y = acc[r][1] * rmv * rsv[1];
        o0.z = acc[r][2] * rmv * rsv[2];
        o0.w = acc[r][3] * rmv * rsv[3];
        o1.x = acc[r][4] * rmv * rsv[4];
        o1.y = acc[r][5] * rmv * rsv[5];
        o1.z = acc[r][6] * rmv * rsv[6];
        o1.w = acc[r][7] * rmv * rsv[7];
        *reinterpret_cast<float4*>(orow + tc * 4)      = o0;
        *reinterpret_cast<float4*>(orow + 64 + tc * 4) = o1;
    }
}

extern "C" void kernel_launch(void* const* d_in, const int* in_sizes, int n_in,
                              void* d_out, int out_size) {
    const float* support = (const float*)d_in[0];
    const float* query   = (const float*)d_in[1];
    float* out = (float*)d_out;

    int total_rows = NQ_ROWS + NS_ROWS;         // 18432 rows, 8 warps/block
    int blocks1 = (total_rows + 7) / 8;
    row_rnorm_kernel<<<blocks1, 256>>>(support, query);

    dim3 grid(1024 / BN, 1024 / BM, 40);
    cosine_gemm_kernel<<<grid, 256>>>(support, query, out);
}

// round 5
// speedup vs baseline: 1.8136x; 1.8136x over previous
#include <cuda_runtime.h>
#include <cuda_bf16.h>
#include <cstdint>

// support: (2,5,1024,128) -> d_in[0]
// query:   (2,4,1024,128) -> d_in[1]
// out:     (2,4,5,1024,1024) fp32
// sim[b,i,j,m,n] = <q_norm[b,i,m,:], s_norm[b,j,n,:]>
//
// bf16 hi/lo split (error compensation) + warp-level mma.sync HMMA path
// (tcgen05 is rejected by the harness's compute_103 virtual arch).
// 3 accumulation passes: hi*hi + hi*lo + lo*hi in fp32 accumulators.

#define NQ_ROWS 8192
#define NS_ROWS 10240
#define KDIM 128
#define KSPLIT 256  // [hi(128) | lo(128)] bf16 per row

__device__ __align__(16) __nv_bfloat16 g_qs[NQ_ROWS * KSPLIT];
__device__ __align__(16) __nv_bfloat16 g_ss[NS_ROWS * KSPLIT];

__device__ __forceinline__ uint32_t smem_u32(const void* p) {
    uint32_t a;
    asm("{ .reg .u64 t; cvta.to.shared.u64 t, %1; cvt.u32.u64 %0, t; }"
        : "=r"(a) : "l"(p));
    return a;
}

__device__ __forceinline__ void ldm_x4(uint32_t* r, uint32_t addr) {
    asm volatile("ldmatrix.sync.aligned.m8n8.x4.shared.b16 {%0,%1,%2,%3}, [%4];"
        : "=r"(r[0]), "=r"(r[1]), "=r"(r[2]), "=r"(r[3]) : "r"(addr));
}

__device__ __forceinline__ void mma16816(float* d, const uint32_t* a,
                                         const uint32_t* b) {
    asm volatile(
        "mma.sync.aligned.m16n8k16.row.col.f32.bf16.bf16.f32 "
        "{%0,%1,%2,%3}, {%4,%5,%6,%7}, {%8,%9}, {%0,%1,%2,%3};"
        : "+f"(d[0]), "+f"(d[1]), "+f"(d[2]), "+f"(d[3])
        : "r"(a[0]), "r"(a[1]), "r"(a[2]), "r"(a[3]), "r"(b[0]), "r"(b[1]));
}

// ---------------------------------------------------------------------------
// Kernel 1: normalize rows, split into bf16 hi/lo. One warp per row.
// ---------------------------------------------------------------------------
__global__ void normalize_split_kernel(const float* __restrict__ s,
                                       const float* __restrict__ q) {
    int warp_id = (blockIdx.x * blockDim.x + threadIdx.x) >> 5;
    int lane    = threadIdx.x & 31;
    if (warp_id >= NQ_ROWS + NS_ROWS) return;

    const float* src;
    __nv_bfloat16* dst;
    if (warp_id < NQ_ROWS) {
        src = q + (size_t)warp_id * KDIM;
        dst = g_qs + (size_t)warp_id * KSPLIT;
    } else {
        int r = warp_id - NQ_ROWS;
        src = s + (size_t)r * KDIM;
        dst = g_ss + (size_t)r * KSPLIT;
    }

    float4 v = reinterpret_cast<const float4*>(src)[lane];
    float ssum = v.x * v.x + v.y * v.y + v.z * v.z + v.w * v.w;
    #pragma unroll
    for (int o = 16; o > 0; o >>= 1)
        ssum += __shfl_xor_sync(0xffffffffu, ssum, o);
    float rn = 1.0f / fmaxf(sqrtf(ssum), 1e-12f);

    float f[4] = {v.x * rn, v.y * rn, v.z * rn, v.w * rn};
    __nv_bfloat162 hi2[2], lo2[2];
    #pragma unroll
    for (int i = 0; i < 2; i++) {
        __nv_bfloat16 h0 = __float2bfloat16_rn(f[2 * i]);
        __nv_bfloat16 h1 = __float2bfloat16_rn(f[2 * i + 1]);
        __nv_bfloat16 l0 = __float2bfloat16_rn(f[2 * i]     - __bfloat162float(h0));
        __nv_bfloat16 l1 = __float2bfloat16_rn(f[2 * i + 1] - __bfloat162float(h1));
        hi2[i] = __nv_bfloat162(h0, h1);
        lo2[i] = __nv_bfloat162(l0, l1);
    }
    *reinterpret_cast<uint2*>(dst + lane * 4)       = *reinterpret_cast<uint2*>(hi2);
    *reinterpret_cast<uint2*>(dst + 128 + lane * 4) = *reinterpret_cast<uint2*>(lo2);
}

// ---------------------------------------------------------------------------
// Kernel 2: HMMA GEMM. 128x128 CTA tile, full K=256 (hi|lo) staged in smem.
// 8 warps, each 64x32. Smem layout: row-major, 512B rows (256 bf16),
// 16B-chunk XOR swizzle: chunk' = chunk ^ (row&7)  -> conflict-free
// staging stores and ldmatrix loads.
// ---------------------------------------------------------------------------
#define A_BYTES 65536
#define B_BYTES 65536
#define SMEM_BYTES (A_BYTES + B_BYTES)

__global__ __launch_bounds__(256)
void cosine_hmma_kernel(float* __restrict__ out) {
    extern __shared__ __align__(128) char smem[];
    char* smA = smem;
    char* smB = smem + A_BYTES;

    int tid  = threadIdx.x;
    int wid  = tid >> 5;
    int lane = tid & 31;

    int p  = blockIdx.z;          // (b*4+i)*5 + j
    int b  = p / 20;
    int ij = p % 20;
    int i  = ij / 5;
    int j  = ij % 5;
    int m0 = blockIdx.y * 128;
    int n0 = blockIdx.x * 128;

    const __nv_bfloat16* abase = g_qs + (size_t)((b * 4 + i) * 1024 + m0) * KSPLIT;
    const __nv_bfloat16* bbase = g_ss + (size_t)((b * 5 + j) * 1024 + n0) * KSPLIT;

    // ---- Stage A and B: 128 rows x 32 chunks (16B) each ----
    #pragma unroll
    for (int it = 0; it < 16; it++) {
        int lin = tid + it * 256;           // 0..4095
        int row = lin >> 5;                 // 0..127
        int ch  = lin & 31;                 // 0..31
        uint32_t doff = (uint32_t)row * 512u + (uint32_t)((ch ^ (row & 7)) << 4);
        uint4 va = *reinterpret_cast<const uint4*>(abase + (size_t)row * KSPLIT + ch * 8);
        *reinterpret_cast<uint4*>(smA + doff) = va;
        uint4 vb = *reinterpret_cast<const uint4*>(bbase + (size_t)row * KSPLIT + ch * 8);
        *reinterpret_cast<uint4*>(smB + doff) = vb;
    }
    __syncthreads();

    // ---- Warp tiling: 2 warps over m (64 each), 4 over n (32 each) ----
    int wm = wid & 1;
    int wn = wid >> 1;
    int mbase = wm * 64;
    int nbase = wn * 32;

    uint32_t smA0 = smem_u32(smA);
    uint32_t smB0 = smem_u32(smB);

    // Per-lane ldmatrix row components.
    // A x4: matrix mi = lane>>3; row = mbase + mt*16 + (mi&1)*8 + (lane&7);
    //       k offset = (mi>>1)*8
    int a_mi   = lane >> 3;
    int a_row0 = mbase + (a_mi & 1) * 8 + (lane & 7);   // + mt*16
    int a_koff = (a_mi >> 1) * 8;
    // B x4: n = nbase + nt2*16 + (mi>>1)*8 + (lane&7); k offset = (mi&1)*8
    int b_row0 = nbase + ((lane >> 4) & 1) * 8 + (lane & 7);  // + nt2*16
    int b_koff = ((lane >> 3) & 1) * 8;

    float acc[4][4][4];
    #pragma unroll
    for (int mt = 0; mt < 4; mt++)
        #pragma unroll
        for (int nt = 0; nt < 4; nt++)
            #pragma unroll
            for (int e = 0; e < 4; e++)
                acc[mt][nt][e] = 0.0f;

    const int KA0[3] = {0, 0, 128};
    const int KB0[3] = {0, 128, 0};

    #pragma unroll
    for (int pass = 0; pass < 3; pass++) {
        #pragma unroll
        for (int ks = 0; ks < 8; ks++) {
            int ka = KA0[pass] + ks * 16 + a_koff;   // bf16 col, multiple of 8
            int kb = KB0[pass] + ks * 16 + b_koff;

            uint32_t aF[4][4];
            #pragma unroll
            for (int mt = 0; mt < 4; mt++) {
                int row = a_row0 + mt * 16;
                uint32_t addr = smA0 + (uint32_t)row * 512u
                              + (uint32_t)((((ka >> 3) ^ (row & 7)) << 4));
                ldm_x4(aF[mt], addr);
            }
            uint32_t bF[2][4];
            #pragma unroll
            for (int nt2 = 0; nt2 < 2; nt2++) {
                int row = b_row0 + nt2 * 16;
                uint32_t addr = smB0 + (uint32_t)row * 512u
                              + (uint32_t)((((kb >> 3) ^ (row & 7)) << 4));
                ldm_x4(bF[nt2], addr);
            }

            #pragma unroll
            for (int mt = 0; mt < 4; mt++) {
                #pragma unroll
                for (int nt = 0; nt < 4; nt++) {
                    // b-frag for n8 tile nt: bF[nt>>1][(nt&1)*2 .. +1]
                    mma16816(acc[mt][nt], aF[mt], &bF[nt >> 1][(nt & 1) * 2]);
                }
            }
        }
    }

    // ---- Epilogue: direct stores, 8B per thread per frag-row (32B/quad) ----
    int tr  = lane >> 2;
    int tc2 = (lane & 3) * 2;
    size_t obase = ((size_t)p << 20)
                 + (size_t)(m0 + mbase) * 1024 + (n0 + nbase);
    #pragma unroll
    for (int mt = 0; mt < 4; mt++) {
        #pragma unroll
        for (int nt = 0; nt < 4; nt++) {
            float* r0 = out + obase + (size_t)(mt * 16 + tr) * 1024 + nt * 8 + tc2;
            float2 v0 = make_float2(acc[mt][nt][0], acc[mt][nt][1]);
            float2 v1 = make_float2(acc[mt][nt][2], acc[mt][nt][3]);
            *reinterpret_cast<float2*>(r0)            = v0;
            *reinterpret_cast<float2*>(r0 + 8 * 1024) = v1;
        }
    }
}

extern "C" void kernel_launch(void* const* d_in, const int* in_sizes, int n_in,
                              void* d_out, int out_size) {
    const float* support = (const float*)d_in[0];
    const float* query   = (const float*)d_in[1];
    float* out = (float*)d_out;

    cudaFuncSetAttribute(cosine_hmma_kernel,
                         cudaFuncAttributeMaxDynamicSharedMemorySize, SMEM_BYTES);

    int total_rows = NQ_ROWS + NS_ROWS;
    int blocks1 = (total_rows + 7) / 8;
    normalize_split_kernel<<<blocks1, 256>>>(support, query);

    dim3 grid(8, 8, 40);
    cosine_hmma_kernel<<<grid, 256, SMEM_BYTES>>>(out);
}

// round 6
// speedup vs baseline: 2.4862x; 1.3708x over previous
#include <cuda_runtime.h>
#include <cuda_bf16.h>
#include <cstdint>

// support: (2,5,1024,128) -> d_in[0]
// query:   (2,4,1024,128) -> d_in[1]
// out:     (2,4,5,1024,1024) fp32
// sim[b,i,j,m,n] = <q_norm[b,i,m,:], s_norm[b,j,n,:]>
//
// bf16 hi/lo split (error compensation) + mma.sync HMMA.
// 3 passes (hi*hi + hi*lo + lo*hi) split into 6 K64 macro-steps,
// double-buffered cp.async pipeline, 64KB smem/CTA -> 2 CTAs/SM.

#define NQ_ROWS 8192
#define NS_ROWS 10240
#define KDIM 128
#define KSPLIT 256  // [hi(128) | lo(128)] bf16 per row

__device__ __align__(16) __nv_bfloat16 g_qs[NQ_ROWS * KSPLIT];
__device__ __align__(16) __nv_bfloat16 g_ss[NS_ROWS * KSPLIT];

__device__ __forceinline__ uint32_t smem_u32(const void* p) {
    uint32_t a;
    asm("{ .reg .u64 t; cvta.to.shared.u64 t, %1; cvt.u32.u64 %0, t; }"
        : "=r"(a) : "l"(p));
    return a;
}

__device__ __forceinline__ void ldm_x4(uint32_t* r, uint32_t addr) {
    asm volatile("ldmatrix.sync.aligned.m8n8.x4.shared.b16 {%0,%1,%2,%3}, [%4];"
        : "=r"(r[0]), "=r"(r[1]), "=r"(r[2]), "=r"(r[3]) : "r"(addr));
}

__device__ __forceinline__ void mma16816(float* d, const uint32_t* a,
                                         const uint32_t* b) {
    asm volatile(
        "mma.sync.aligned.m16n8k16.row.col.f32.bf16.bf16.f32 "
        "{%0,%1,%2,%3}, {%4,%5,%6,%7}, {%8,%9}, {%0,%1,%2,%3};"
        : "+f"(d[0]), "+f"(d[1]), "+f"(d[2]), "+f"(d[3])
        : "r"(a[0]), "r"(a[1]), "r"(a[2]), "r"(a[3]), "r"(b[0]), "r"(b[1]));
}

#define CP_ASYNC16(dst, src) \
    asm volatile("cp.async.cg.shared.global [%0], [%1], 16;" \
        :: "r"(dst), "l"(src) : "memory")
#define CP_COMMIT() asm volatile("cp.async.commit_group;" ::: "memory")
#define CP_WAIT(n)  asm volatile("cp.async.wait_group %0;" :: "n"(n) : "memory")

// ---------------------------------------------------------------------------
// Kernel 1: normalize rows, split into bf16 hi/lo. One warp per row.
// ---------------------------------------------------------------------------
__global__ void normalize_split_kernel(const float* __restrict__ s,
                                       const float* __restrict__ q) {
    int warp_id = (blockIdx.x * blockDim.x + threadIdx.x) >> 5;
    int lane    = threadIdx.x & 31;
    if (warp_id >= NQ_ROWS + NS_ROWS) return;

    const float* src;
    __nv_bfloat16* dst;
    if (warp_id < NQ_ROWS) {
        src = q + (size_t)warp_id * KDIM;
        dst = g_qs + (size_t)warp_id * KSPLIT;
    } else {
        int r = warp_id - NQ_ROWS;
        src = s + (size_t)r * KDIM;
        dst = g_ss + (size_t)r * KSPLIT;
    }

    float4 v = reinterpret_cast<const float4*>(src)[lane];
    float ssum = v.x * v.x + v.y * v.y + v.z * v.z + v.w * v.w;
    #pragma unroll
    for (int o = 16; o > 0; o >>= 1)
        ssum += __shfl_xor_sync(0xffffffffu, ssum, o);
    float rn = 1.0f / fmaxf(sqrtf(ssum), 1e-12f);

    float f[4] = {v.x * rn, v.y * rn, v.z * rn, v.w * rn};
    __nv_bfloat162 hi2[2], lo2[2];
    #pragma unroll
    for (int i = 0; i < 2; i++) {
        __nv_bfloat16 h0 = __float2bfloat16_rn(f[2 * i]);
        __nv_bfloat16 h1 = __float2bfloat16_rn(f[2 * i + 1]);
        __nv_bfloat16 l0 = __float2bfloat16_rn(f[2 * i]     - __bfloat162float(h0));
        __nv_bfloat16 l1 = __float2bfloat16_rn(f[2 * i + 1] - __bfloat162float(h1));
        hi2[i] = __nv_bfloat162(h0, h1);
        lo2[i] = __nv_bfloat162(l0, l1);
    }
    *reinterpret_cast<uint2*>(dst + lane * 4)       = *reinterpret_cast<uint2*>(hi2);
    *reinterpret_cast<uint2*>(dst + 128 + lane * 4) = *reinterpret_cast<uint2*>(lo2);
}

// ---------------------------------------------------------------------------
// Kernel 2: pipelined HMMA GEMM. CTA tile 128x128, 8 warps (warp 64x32).
// 6 macro-steps of K64; chunk buffers: A 16KB + B 16KB, double buffered
// (64KB total). Rows are 64 bf16 = 128B with 16B-chunk XOR swizzle.
// ---------------------------------------------------------------------------
#define CHUNK_A 16384
#define CHUNK_B 16384
#define BUF_BYTES (CHUNK_A + CHUNK_B)   // 32KB per stage
#define SMEM_BYTES (2 * BUF_BYTES)      // 64KB

__global__ __launch_bounds__(256, 2)
void cosine_hmma_kernel(float* __restrict__ out) {
    extern __shared__ __align__(1024) char smem[];

    int tid  = threadIdx.x;
    int wid  = tid >> 5;
    int lane = tid & 31;

    int p  = blockIdx.z;          // (b*4+i)*5 + j
    int b  = p / 20;
    int ij = p % 20;
    int i  = ij / 5;
    int j  = ij % 5;
    int m0 = blockIdx.y * 128;
    int n0 = blockIdx.x * 128;

    const __nv_bfloat16* abase = g_qs + (size_t)((b * 4 + i) * 1024 + m0) * KSPLIT;
    const __nv_bfloat16* bbase = g_ss + (size_t)((b * 5 + j) * 1024 + n0) * KSPLIT;

    // Source column base (in g_* KSPLIT layout) per macro step.
    const int ACOL[6] = {0, 64, 0, 64, 128, 192};
    const int BCOL[6] = {0, 64, 128, 192, 0, 64};

    // Staging indices: per thread 4 A rows-chunks + 4 B (1024 16B ops each).
    int st_row = tid >> 1;               // used via lin below
    (void)st_row;

    uint32_t smem0 = smem_u32(smem);

    // ---- issue cp.async loads for macro step s into buffer (s&1) ----
    auto load_step = [&](int s) {
        uint32_t bufA = smem0 + (uint32_t)(s & 1) * BUF_BYTES;
        uint32_t bufB = bufA + CHUNK_A;
        int ac = ACOL[s], bc = BCOL[s];
        #pragma unroll
        for (int it = 0; it < 4; it++) {
            int lin = tid + it * 256;    // 0..1023
            int row = lin >> 3;          // 0..127
            int ch  = lin & 7;           // 0..7 (16B chunks of 128B row)
            uint32_t doff = (uint32_t)row * 128u + (uint32_t)((ch ^ (row & 7)) << 4);
            CP_ASYNC16(bufA + doff,
                       abase + (size_t)row * KSPLIT + ac + ch * 8);
            CP_ASYNC16(bufB + doff,
                       bbase + (size_t)row * KSPLIT + bc + ch * 8);
        }
        CP_COMMIT();
    };

    // ---- warp tiling ----
    int wm = wid & 1;
    int wn = wid >> 1;
    int mbase = wm * 64;
    int nbase = wn * 32;

    int a_mi   = lane >> 3;
    int a_row0 = mbase + (a_mi & 1) * 8 + (lane & 7);     // + mt*16
    int a_koff = (a_mi >> 1) * 8;
    int b_row0 = nbase + ((lane >> 4) & 1) * 8 + (lane & 7);  // + nt2*16
    int b_koff = ((lane >> 3) & 1) * 8;

    float acc[4][4][4];
    #pragma unroll
    for (int mt = 0; mt < 4; mt++)
        #pragma unroll
        for (int nt = 0; nt < 4; nt++)
            #pragma unroll
            for (int e = 0; e < 4; e++)
                acc[mt][nt][e] = 0.0f;

    load_step(0);

    #pragma unroll
    for (int s = 0; s < 6; s++) {
        if (s + 1 < 6) {
            load_step(s + 1);
            CP_WAIT(1);      // step s data resident
        } else {
            CP_WAIT(0);
        }
        __syncthreads();

        uint32_t bufA = smem0 + (uint32_t)(s & 1) * BUF_BYTES;
        uint32_t bufB = bufA + CHUNK_A;

        #pragma unroll
        for (int ks = 0; ks < 4; ks++) {
            int ka = ks * 16 + a_koff;   // within-chunk col, multiple of 8
            int kb = ks * 16 + b_koff;

            uint32_t aF[4][4];
            #pragma unroll
            for (int mt = 0; mt < 4; mt++) {
                int row = a_row0 + mt * 16;
                uint32_t addr = bufA + (uint32_t)row * 128u
                              + (uint32_t)((((ka >> 3) ^ (row & 7)) << 4));
                ldm_x4(aF[mt], addr);
            }
            uint32_t bF[2][4];
            #pragma unroll
            for (int nt2 = 0; nt2 < 2; nt2++) {
                int row = b_row0 + nt2 * 16;
                uint32_t addr = bufB + (uint32_t)row * 128u
                              + (uint32_t)((((kb >> 3) ^ (row & 7)) << 4));
                ldm_x4(bF[nt2], addr);
            }

            #pragma unroll
            for (int mt = 0; mt < 4; mt++)
                #pragma unroll
                for (int nt = 0; nt < 4; nt++)
                    mma16816(acc[mt][nt], aF[mt], &bF[nt >> 1][(nt & 1) * 2]);
        }
        __syncthreads();   // all warps done with buf (s&1) before reuse
    }

    // ---- Epilogue: direct fragment stores (32B contiguous per quad) ----
    int tr  = lane >> 2;
    int tc2 = (lane & 3) * 2;
    size_t obase = ((size_t)p << 20)
                 + (size_t)(m0 + mbase) * 1024 + (n0 + nbase);
    #pragma unroll
    for (int mt = 0; mt < 4; mt++) {
        #pragma unroll
        for (int nt = 0; nt < 4; nt++) {
            float* r0 = out + obase + (size_t)(mt * 16 + tr) * 1024 + nt * 8 + tc2;
            *reinterpret_cast<float2*>(r0) =
                make_float2(acc[mt][nt][0], acc[mt][nt][1]);
            *reinterpret_cast<float2*>(r0 + 8 * 1024) =
                make_float2(acc[mt][nt][2], acc[mt][nt][3]);
        }
    }
}

extern "C" void kernel_launch(void* const* d_in, const int* in_sizes, int n_in,
                              void* d_out, int out_size) {
    const float* support = (const float*)d_in[0];
    const float* query   = (const float*)d_in[1];
    float* out = (float*)d_out;

    cudaFuncSetAttribute(cosine_hmma_kernel,
                         cudaFuncAttributeMaxDynamicSharedMemorySize, SMEM_BYTES);

    int total_rows = NQ_ROWS + NS_ROWS;
    int blocks1 = (total_rows + 7) / 8;
    normalize_split_kernel<<<blocks1, 256>>>(support, query);

    dim3 grid(8, 8, 40);
    cosine_hmma_kernel<<<grid, 256, SMEM_BYTES>>>(out);
}